// round 2
// baseline (speedup 1.0000x reference)
#include <cuda_runtime.h>
#include <cuda_bf16.h>
#include <math.h>

// Problem constants
constexpr int cB = 8, cS = 512, cT = 512, cH = 16, cHK = 64, cD = 1024, cF = 4096;
constexpr int SB = 32;   // s-rows per attention block
constexpr int TT = 64;   // t-tile width

// ---------------- scratch (device globals; no allocation allowed) ----------------
__device__ float g_q  [(size_t)cB * cS * cD];
__device__ float g_k  [(size_t)cB * cS * cD];
__device__ float g_v  [(size_t)cB * cS * cD];
__device__ float g_ctx[(size_t)cB * cS * cD];
__device__ float g_tmp[(size_t)cB * cS * cD];
__device__ float g_o1 [(size_t)cB * cS * cD];
__device__ float g_o2 [(size_t)cB * cS * cD];
__device__ float g_h  [(size_t)cB * cS * cF];

// ---------------- 128x128 tiled SGEMM, BK=8, 256 thr, 8x8/thread, double-buffered --
// C[M,N] = A[M,K] @ B[K,N] + bias[N], optional relu. M%128==0, N%128==0, K%8==0.
__global__ __launch_bounds__(256, 2)
void gemm128_kernel(const float* __restrict__ A,
                    const float* __restrict__ Bm,
                    const float* __restrict__ bias,
                    float* __restrict__ C,
                    int M, int N, int Kd, int relu)
{
    __shared__ float As[2][8][128];   // [buf][k][m]
    __shared__ float Bs[2][8][128];   // [buf][k][n]

    const int tid  = threadIdx.x;
    const int m0   = blockIdx.y * 128, n0 = blockIdx.x * 128;
    const int warp = tid >> 5, lane = tid & 31;
    const int warpX = warp >> 2, warpY = warp & 3;   // 2 x 4 warps
    const int lx = lane & 7, ly = lane >> 3;         // 8 x 4 lanes
    const int rowA = warpY * 32 + ly * 4;            // rows rowA..+3, rowA+16..+19
    const int colB = warpX * 64 + lx * 4;            // cols colB..+3, colB+32..+35

    // global-load assignments
    const int Ar = tid >> 1, Ac = (tid & 1) * 4;     // A: 128 rows x 8 cols
    const int Br = tid >> 5, Bc = (tid & 31) * 4;    // B: 8 rows x 128 cols

    const float* Aptr = A + (size_t)(m0 + Ar) * Kd + Ac;
    const float* Bptr = Bm + (size_t)Br * N + n0 + Bc;

    float acc[8][8] = {};

    // prime buffer 0
    float4 ra = *(const float4*)(Aptr);
    float4 rb = *(const float4*)(Bptr);
    As[0][Ac + 0][Ar] = ra.x; As[0][Ac + 1][Ar] = ra.y;
    As[0][Ac + 2][Ar] = ra.z; As[0][Ac + 3][Ar] = ra.w;
    *(float4*)&Bs[0][Br][Bc] = rb;
    __syncthreads();

    const int KT = Kd >> 3;
    int buf = 0;
    for (int kt = 0; kt < KT; kt++) {
        const bool more = (kt + 1 < KT);
        if (more) {
            ra = *(const float4*)(Aptr + (kt + 1) * 8);
            rb = *(const float4*)(Bptr + (size_t)(kt + 1) * 8 * N);
        }
        #pragma unroll
        for (int k = 0; k < 8; k++) {
            float4 a0 = *(const float4*)&As[buf][k][rowA];
            float4 a1 = *(const float4*)&As[buf][k][rowA + 16];
            float4 b0 = *(const float4*)&Bs[buf][k][colB];
            float4 b1 = *(const float4*)&Bs[buf][k][colB + 32];
            float aa[8] = {a0.x, a0.y, a0.z, a0.w, a1.x, a1.y, a1.z, a1.w};
            float bb[8] = {b0.x, b0.y, b0.z, b0.w, b1.x, b1.y, b1.z, b1.w};
            #pragma unroll
            for (int i = 0; i < 8; i++)
                #pragma unroll
                for (int j = 0; j < 8; j++)
                    acc[i][j] += aa[i] * bb[j];
        }
        if (more) {
            const int nb = buf ^ 1;
            As[nb][Ac + 0][Ar] = ra.x; As[nb][Ac + 1][Ar] = ra.y;
            As[nb][Ac + 2][Ar] = ra.z; As[nb][Ac + 3][Ar] = ra.w;
            *(float4*)&Bs[nb][Br][Bc] = rb;
            __syncthreads();
            buf = nb;
        }
    }

    // epilogue: bias (+relu), float4 stores
    #pragma unroll
    for (int i = 0; i < 8; i++) {
        const int m = m0 + rowA + ((i < 4) ? i : (12 + i));   // i>=4 -> +16+(i-4)
        float4 o0, o1;
        float* p0 = &o0.x; float* p1 = &o1.x;
        #pragma unroll
        for (int j = 0; j < 4; j++) {
            float v0 = acc[i][j]     + bias[n0 + colB + j];
            float v1 = acc[i][j + 4] + bias[n0 + colB + 32 + j];
            if (relu) { v0 = fmaxf(v0, 0.f); v1 = fmaxf(v1, 0.f); }
            p0[j] = v0; p1[j] = v1;
        }
        *(float4*)&C[(size_t)m * N + n0 + colB]      = o0;
        *(float4*)&C[(size_t)m * N + n0 + colB + 32] = o1;
    }
}

// ---------------- fused attention: scores -> softmax -> attn write -> ctx ----------
// One block per (b, h, 32-row s tile). Q/K/V layout [B,S,H,K]. attn_out [B,H,S,T].
template <int CAUSAL>
__global__ void attn_kernel(const float* __restrict__ Q,
                            const float* __restrict__ Kb,
                            const float* __restrict__ Vb,
                            float* __restrict__ attn_out,
                            float* __restrict__ ctx)
{
    extern __shared__ float sm[];
    float* sc  = sm;                    // [SB][cT]  scores -> attn weights
    float* Qs  = sm + SB * cT;          // [SB][65]
    float* KVs = Qs + SB * 65;          // [TT][65]

    const int tid = threadIdx.x;
    const int s0  = blockIdx.x * SB;
    const int h   = blockIdx.y;
    const int b   = blockIdx.z;
    const size_t base = ((size_t)(b * cS) * cH + h) * cHK;   // + s*cH*cHK + k
    const int rowStride = cH * cHK;

    // load Q tile [SB][cHK]
    for (int e = tid; e < SB * cHK; e += 256) {
        int r = e >> 6, k = e & 63;
        Qs[r * 65 + k] = Q[base + (size_t)(s0 + r) * rowStride + k];
    }

    const int ntiles = CAUSAL ? ((s0 + SB - 1) / TT + 1) : (cT / TT);
    const int r  = tid >> 3;      // 0..31
    const int jb = tid & 7;       // 0..7 ; cols jb + 8*j

    // ---- scores ----
    for (int tile = 0; tile < ntiles; tile++) {
        const int t0 = tile * TT;
        __syncthreads();
        for (int e = tid; e < TT * cHK; e += 256) {
            int tr = e >> 6, k = e & 63;
            KVs[tr * 65 + k] = Kb[base + (size_t)(t0 + tr) * rowStride + k];
        }
        __syncthreads();
        float acc[8] = {};
        #pragma unroll 16
        for (int k = 0; k < cHK; k++) {
            float qv = Qs[r * 65 + k];
            #pragma unroll
            for (int j = 0; j < 8; j++)
                acc[j] += qv * KVs[(jb + 8 * j) * 65 + k];
        }
        #pragma unroll
        for (int j = 0; j < 8; j++)
            sc[r * cT + t0 + jb + 8 * j] = acc[j] * 0.125f;   // 1/sqrt(64)
    }
    __syncthreads();

    // ---- softmax + attn write (warp per row group) ----
    {
        const int warp = tid >> 5, lane = tid & 31;
        float vals[16];
        for (int rr = 0; rr < 4; rr++) {
            const int row = warp * 4 + rr;
            const int sg  = s0 + row;
            float m = -1e30f;
            #pragma unroll
            for (int i = 0; i < 16; i++) {
                int t = lane + 32 * i;
                float vv = sc[row * cT + t];
                if (CAUSAL && t > sg) vv = -1e9f;
                vals[i] = vv;
                m = fmaxf(m, vv);
            }
            #pragma unroll
            for (int o = 16; o; o >>= 1) m = fmaxf(m, __shfl_xor_sync(0xffffffffu, m, o));
            float sum = 0.f;
            #pragma unroll
            for (int i = 0; i < 16; i++) { vals[i] = __expf(vals[i] - m); sum += vals[i]; }
            #pragma unroll
            for (int o = 16; o; o >>= 1) sum += __shfl_xor_sync(0xffffffffu, sum, o);
            const float inv = 1.f / sum;
            const size_t obase = ((size_t)(b * cH + h) * cS + sg) * cT;
            #pragma unroll
            for (int i = 0; i < 16; i++) {
                int t = lane + 32 * i;
                float p = vals[i] * inv;
                sc[row * cT + t] = p;
                attn_out[obase + t] = p;
            }
        }
    }
    __syncthreads();

    // ---- ctx = attn @ V ----
    float cacc[8] = {};
    for (int tile = 0; tile < ntiles; tile++) {
        const int t0 = tile * TT;
        __syncthreads();
        for (int e = tid; e < TT * cHK; e += 256) {
            int tr = e >> 6, k = e & 63;
            KVs[tr * 65 + k] = Vb[base + (size_t)(t0 + tr) * rowStride + k];
        }
        __syncthreads();
        #pragma unroll 16
        for (int k = 0; k < TT; k++) {
            float a = sc[r * cT + t0 + k];
            #pragma unroll
            for (int j = 0; j < 8; j++)
                cacc[j] += a * KVs[k * 65 + jb + 8 * j];
        }
    }
    #pragma unroll
    for (int j = 0; j < 8; j++)
        ctx[base + (size_t)(s0 + r) * rowStride + jb + 8 * j] = cacc[j];
}

// ---------------- add-residual + layernorm, one block per row (D=1024) -------------
__global__ void add_ln_kernel(const float* __restrict__ a,
                              const float* __restrict__ res,
                              const float* __restrict__ g,
                              const float* __restrict__ be,
                              float* __restrict__ out)
{
    __shared__ float red[8];
    __shared__ float stat;
    const int row = blockIdx.x, tid = threadIdx.x;
    const size_t base = (size_t)row * cD;
    float v[4]; float s = 0.f;
    #pragma unroll
    for (int i = 0; i < 4; i++) {
        int c = tid + 256 * i;
        float t = a[base + c] + res[base + c];
        v[i] = t; s += t;
    }
    #pragma unroll
    for (int o = 16; o; o >>= 1) s += __shfl_xor_sync(0xffffffffu, s, o);
    if ((tid & 31) == 0) red[tid >> 5] = s;
    __syncthreads();
    if (tid == 0) { float t = 0; for (int i = 0; i < 8; i++) t += red[i]; stat = t * (1.f / cD); }
    __syncthreads();
    const float mu = stat;
    float s2 = 0.f;
    #pragma unroll
    for (int i = 0; i < 4; i++) { float d = v[i] - mu; s2 += d * d; }
    #pragma unroll
    for (int o = 16; o; o >>= 1) s2 += __shfl_xor_sync(0xffffffffu, s2, o);
    __syncthreads();
    if ((tid & 31) == 0) red[tid >> 5] = s2;
    __syncthreads();
    if (tid == 0) { float t = 0; for (int i = 0; i < 8; i++) t += red[i];
                    stat = rsqrtf(t * (1.f / cD) + 1e-6f); }
    __syncthreads();
    const float rstd = stat;
    #pragma unroll
    for (int i = 0; i < 4; i++) {
        int c = tid + 256 * i;
        out[base + c] = (v[i] - mu) * rstd * g[c] + be[c];
    }
}

// ---------------- launch ------------------------------------------------------------
extern "C" void kernel_launch(void* const* d_in, const int* in_sizes, int n_in,
                              void* d_out, int out_size)
{
    // metadata order (mask at [2] is ignored; causal predicate computed analytically)
    const float* x    = (const float*)d_in[0];
    const float* enc  = (const float*)d_in[1];
    const float* wq1  = (const float*)d_in[3];  const float* bq1 = (const float*)d_in[4];
    const float* wk1  = (const float*)d_in[5];  const float* bk1 = (const float*)d_in[6];
    const float* wv1  = (const float*)d_in[7];  const float* bv1 = (const float*)d_in[8];
    const float* wo1  = (const float*)d_in[9];  const float* bo1 = (const float*)d_in[10];
    const float* wq2  = (const float*)d_in[11]; const float* bq2 = (const float*)d_in[12];
    const float* wk2  = (const float*)d_in[13]; const float* bk2 = (const float*)d_in[14];
    const float* wv2  = (const float*)d_in[15]; const float* bv2 = (const float*)d_in[16];
    const float* wo2  = (const float*)d_in[17]; const float* bo2 = (const float*)d_in[18];
    const float* g1   = (const float*)d_in[19]; const float* be1 = (const float*)d_in[20];
    const float* g2   = (const float*)d_in[21]; const float* be2 = (const float*)d_in[22];
    const float* g3   = (const float*)d_in[23]; const float* be3 = (const float*)d_in[24];
    const float* wf1  = (const float*)d_in[25]; const float* bf1 = (const float*)d_in[26];
    const float* wf2  = (const float*)d_in[27]; const float* bf2 = (const float*)d_in[28];

    float* out   = (float*)d_out;
    float* attn1 = out + (size_t)cB * cS * cD;
    float* attn2 = attn1 + (size_t)cB * cH * cS * cS;

    float *q, *k, *v, *ctx, *tmp, *o1, *o2, *hb;
    cudaGetSymbolAddress((void**)&q,   g_q);
    cudaGetSymbolAddress((void**)&k,   g_k);
    cudaGetSymbolAddress((void**)&v,   g_v);
    cudaGetSymbolAddress((void**)&ctx, g_ctx);
    cudaGetSymbolAddress((void**)&tmp, g_tmp);
    cudaGetSymbolAddress((void**)&o1,  g_o1);
    cudaGetSymbolAddress((void**)&o2,  g_o2);
    cudaGetSymbolAddress((void**)&hb,  g_h);

    const int smemAttn = (SB * cT + SB * 65 + TT * 65) * (int)sizeof(float); // 90496 B
    cudaFuncSetAttribute(attn_kernel<1>, cudaFuncAttributeMaxDynamicSharedMemorySize, smemAttn);
    cudaFuncSetAttribute(attn_kernel<0>, cudaFuncAttributeMaxDynamicSharedMemorySize, smemAttn);

    const int M = cB * cS;               // 4096
    dim3 gP(cD / 128, M / 128);          // N=1024 GEMMs: 8 x 32
    dim3 gF1(cF / 128, M / 128);         // N=4096 GEMM : 32 x 32
    dim3 gA(cS / SB, cH, cB);            // attention blocks

    // ---- mha1 (self, causal) ----
    gemm128_kernel<<<gP, 256>>>(x, wq1, bq1, q, M, cD, cD, 0);
    gemm128_kernel<<<gP, 256>>>(x, wk1, bk1, k, M, cD, cD, 0);
    gemm128_kernel<<<gP, 256>>>(x, wv1, bv1, v, M, cD, cD, 0);
    attn_kernel<1><<<gA, 256, smemAttn>>>(q, k, v, attn1, ctx);
    gemm128_kernel<<<gP, 256>>>(ctx, wo1, bo1, tmp, M, cD, cD, 0);
    add_ln_kernel<<<M, 256>>>(tmp, x, g1, be1, o1);

    // ---- mha2 (cross) ----
    gemm128_kernel<<<gP, 256>>>(o1,  wq2, bq2, q, M, cD, cD, 0);
    gemm128_kernel<<<gP, 256>>>(enc, wk2, bk2, k, M, cD, cD, 0);
    gemm128_kernel<<<gP, 256>>>(enc, wv2, bv2, v, M, cD, cD, 0);
    attn_kernel<0><<<gA, 256, smemAttn>>>(q, k, v, attn2, ctx);
    gemm128_kernel<<<gP, 256>>>(ctx, wo2, bo2, tmp, M, cD, cD, 0);
    add_ln_kernel<<<M, 256>>>(tmp, o1, g2, be2, o2);

    // ---- ffn ----
    gemm128_kernel<<<gF1, 256>>>(o2, wf1, bf1, hb, M, cF, cD, 1);
    gemm128_kernel<<<gP, 256>>>(hb, wf2, bf2, tmp, M, cD, cF, 0);
    add_ln_kernel<<<M, 256>>>(tmp, o2, g3, be3, out);
}

// round 6
// speedup vs baseline: 1.3464x; 1.3464x over previous
#include <cuda_runtime.h>
#include <cuda_bf16.h>
#include <cstdint>
#include <math.h>

// Problem constants
constexpr int cB = 8, cS = 512, cT = 512, cH = 16, cHK = 64, cD = 1024, cF = 4096;
constexpr int SB = 32;   // s-rows per attention block
constexpr int TT = 64;   // t-tile width

// ---------------- scratch (device globals; no allocation allowed) ----------------
__device__ float g_q  [(size_t)cB * cS * cD];
__device__ float g_k  [(size_t)cB * cS * cD];
__device__ float g_v  [(size_t)cB * cS * cD];
__device__ float g_ctx[(size_t)cB * cS * cD];
__device__ float g_tmp[(size_t)cB * cS * cD];
__device__ float g_o1 [(size_t)cB * cS * cD];
__device__ float g_o2 [(size_t)cB * cS * cD];
__device__ float g_h  [(size_t)cB * cS * cF];
__device__ float g_wt [(size_t)16 * 1024 * 1024];   // transposed weights (fp32)

__device__ __forceinline__ uint32_t smem_u32(const void* p) {
    uint32_t a;
    asm("{ .reg .u64 t; cvta.to.shared.u64 t, %1; cvt.u32.u64 %0, t; }" : "=r"(a) : "l"(p));
    return a;
}

#define LDSM_X4(r0, r1, r2, r3, addr)                                             \
    asm volatile("ldmatrix.sync.aligned.m8n8.x4.shared.b16 {%0,%1,%2,%3}, [%4];"  \
                 : "=r"(r0), "=r"(r1), "=r"(r2), "=r"(r3) : "r"(addr))

#define MMA16816(d, a, b0, b1)                                                    \
    asm volatile("mma.sync.aligned.m16n8k16.row.col.f32.bf16.bf16.f32 "           \
                 "{%0,%1,%2,%3}, {%4,%5,%6,%7}, {%8,%9}, {%0,%1,%2,%3};"          \
                 : "+f"((d)[0]), "+f"((d)[1]), "+f"((d)[2]), "+f"((d)[3])         \
                 : "r"((a)[0]), "r"((a)[1]), "r"((a)[2]), "r"((a)[3]),            \
                   "r"(b0), "r"(b1))

// ---------------- weight transpose (fp32): dst[c][r] = src[r][c] -------------------
__global__ void transpose_kernel(const float* __restrict__ src, float* __restrict__ dst,
                                 int R, int Ccols)
{
    __shared__ float t[32][33];
    const int c0 = blockIdx.x * 32, r0 = blockIdx.y * 32;
    const int x = threadIdx.x, y = threadIdx.y;
    #pragma unroll
    for (int i = 0; i < 32; i += 8)
        t[y + i][x] = src[(size_t)(r0 + y + i) * Ccols + c0 + x];
    __syncthreads();
    #pragma unroll
    for (int i = 0; i < 32; i += 8)
        dst[(size_t)(c0 + y + i) * R + r0 + x] = t[x][y + i];
}

// ---------------- HMMA bf16 GEMM with 3x-bf16 split --------------------------------
// C[M,N] = A[M,Kd] @ Bt[N,Kd]^T + bias[N], opt relu.
// BM=128, BN=128, BK=32, 256 thr (8 warps, 4x2), warp tile 32x64.
constexpr int LDT = 40;                     // bf16 elems per smem row (32 + 8 pad)
constexpr int TILE_B16 = 128 * LDT;         // 5120 bf16 = 10240 B per tile
constexpr int MM_BUF = 4 * TILE_B16;        // Ah, Al, Bh, Bl per stage (bf16 elems)
constexpr int MM_SMEM = 2 * MM_BUF * 2;     // bytes: 81920

__global__ __launch_bounds__(256, 1)
void mma_gemm(const float* __restrict__ A, const float* __restrict__ Bt,
              const float* __restrict__ bias, float* __restrict__ C,
              int N, int Kd, int relu)
{
    extern __shared__ __nv_bfloat16 smb[];
    const int tid = threadIdx.x;
    const int lane = tid & 31, warp = tid >> 5;
    const int m0 = blockIdx.y * 128, n0 = blockIdx.x * 128;
    const int wm0 = (warp & 3) * 32, wn0 = (warp >> 2) * 64;

    // smem tile bases (bf16-element offsets)
    __nv_bfloat16* Ah[2]; __nv_bfloat16* Al[2];
    __nv_bfloat16* Bh[2]; __nv_bfloat16* Bl[2];
    #pragma unroll
    for (int s = 0; s < 2; s++) {
        __nv_bfloat16* p = smb + s * MM_BUF;
        Ah[s] = p; Al[s] = p + TILE_B16; Bh[s] = p + 2 * TILE_B16; Bl[s] = p + 3 * TILE_B16;
    }

    // global load mapping: 4 float4 per thread per operand tile (128x32 fp32)
    int arow[4], ac4[4];
    #pragma unroll
    for (int i = 0; i < 4; i++) { int f = tid + 256 * i; arow[i] = f >> 3; ac4[i] = f & 7; }

    float4 pa[4], pb[4];
    auto load_global = [&](int c) {
        #pragma unroll
        for (int i = 0; i < 4; i++) {
            pa[i] = *(const float4*)(A  + (size_t)(m0 + arow[i]) * Kd + c * 32 + ac4[i] * 4);
            pb[i] = *(const float4*)(Bt + (size_t)(n0 + arow[i]) * Kd + c * 32 + ac4[i] * 4);
        }
    };
    auto cvt_store = [&](int s) {
        #pragma unroll
        for (int i = 0; i < 4; i++) {
            int off = arow[i] * LDT + ac4[i] * 4;
            const float va[4] = {pa[i].x, pa[i].y, pa[i].z, pa[i].w};
            const float vb[4] = {pb[i].x, pb[i].y, pb[i].z, pb[i].w};
            #pragma unroll
            for (int e = 0; e < 4; e++) {
                __nv_bfloat16 h = __float2bfloat16(va[e]);
                Ah[s][off + e] = h;
                Al[s][off + e] = __float2bfloat16(va[e] - __bfloat162float(h));
                __nv_bfloat16 hb = __float2bfloat16(vb[e]);
                Bh[s][off + e] = hb;
                Bl[s][off + e] = __float2bfloat16(vb[e] - __bfloat162float(hb));
            }
        }
    };

    float acc[2][8][4] = {};

    // ldmatrix address offsets (bytes)
    const int aoff = (wm0 + (lane & 15)) * LDT + ((lane >> 4) << 3);        // + mf*16*LDT
    const int boff = (wn0 + (((lane >> 4) & 1) << 3) + (lane & 7)) * LDT
                   + (((lane >> 3) & 1) << 3);                              // + j*8*LDT (+kk)

    const int NC = Kd >> 5;
    load_global(0);
    cvt_store(0);
    __syncthreads();

    for (int c = 0; c < NC; c++) {
        const int buf = c & 1;
        if (c + 1 < NC) load_global(c + 1);

        const uint32_t sAh = smem_u32(Ah[buf]), sAl = smem_u32(Al[buf]);
        const uint32_t sBh = smem_u32(Bh[buf]), sBl = smem_u32(Bl[buf]);
        #pragma unroll
        for (int kk = 0; kk < 32; kk += 16) {
            uint32_t ah[2][4], al[2][4];
            #pragma unroll
            for (int mf = 0; mf < 2; mf++) {
                uint32_t adr = (uint32_t)((aoff + mf * 16 * LDT + kk) * 2);
                LDSM_X4(ah[mf][0], ah[mf][1], ah[mf][2], ah[mf][3], sAh + adr);
                LDSM_X4(al[mf][0], al[mf][1], al[mf][2], al[mf][3], sAl + adr);
            }
            #pragma unroll
            for (int j = 0; j < 8; j += 2) {
                uint32_t bh[4], bl[4];
                uint32_t adr = (uint32_t)((boff + j * 8 * LDT + kk) * 2);
                LDSM_X4(bh[0], bh[1], bh[2], bh[3], sBh + adr);
                LDSM_X4(bl[0], bl[1], bl[2], bl[3], sBl + adr);
                #pragma unroll
                for (int mf = 0; mf < 2; mf++) {
                    MMA16816(acc[mf][j],     ah[mf], bh[0], bh[1]);
                    MMA16816(acc[mf][j],     al[mf], bh[0], bh[1]);
                    MMA16816(acc[mf][j],     ah[mf], bl[0], bl[1]);
                    MMA16816(acc[mf][j + 1], ah[mf], bh[2], bh[3]);
                    MMA16816(acc[mf][j + 1], al[mf], bh[2], bh[3]);
                    MMA16816(acc[mf][j + 1], ah[mf], bl[2], bl[3]);
                }
            }
        }
        if (c + 1 < NC) cvt_store(buf ^ 1);
        __syncthreads();
    }

    // epilogue: fragment layout d0,d1 -> (row, col..col+1), d2,d3 -> (row+8, ..)
    #pragma unroll
    for (int mf = 0; mf < 2; mf++) {
        const int row = m0 + wm0 + mf * 16 + (lane >> 2);
        #pragma unroll
        for (int j = 0; j < 8; j++) {
            const int col = n0 + wn0 + j * 8 + (lane & 3) * 2;
            const float b0 = bias[col], b1 = bias[col + 1];
            float2 v0 = { acc[mf][j][0] + b0, acc[mf][j][1] + b1 };
            float2 v1 = { acc[mf][j][2] + b0, acc[mf][j][3] + b1 };
            if (relu) {
                v0.x = fmaxf(v0.x, 0.f); v0.y = fmaxf(v0.y, 0.f);
                v1.x = fmaxf(v1.x, 0.f); v1.y = fmaxf(v1.y, 0.f);
            }
            *(float2*)&C[(size_t)row * N + col]       = v0;
            *(float2*)&C[(size_t)(row + 8) * N + col] = v1;
        }
    }
}

// ---------------- fused attention: scores -> softmax -> attn write -> ctx ----------
template <int CAUSAL>
__global__ void attn_kernel(const float* __restrict__ Q,
                            const float* __restrict__ Kb,
                            const float* __restrict__ Vb,
                            float* __restrict__ attn_out,
                            float* __restrict__ ctx)
{
    extern __shared__ float sm[];
    float* sc  = sm;                    // [SB][cT]
    float* Qs  = sm + SB * cT;          // [SB][65]
    float* KVs = Qs + SB * 65;          // [TT][65]

    const int tid = threadIdx.x;
    const int s0  = blockIdx.x * SB;
    const int h   = blockIdx.y;
    const int b   = blockIdx.z;
    const size_t base = ((size_t)(b * cS) * cH + h) * cHK;
    const int rowStride = cH * cHK;

    for (int e = tid; e < SB * cHK; e += 256) {
        int r = e >> 6, k = e & 63;
        Qs[r * 65 + k] = Q[base + (size_t)(s0 + r) * rowStride + k];
    }

    const int ntiles = CAUSAL ? ((s0 + SB - 1) / TT + 1) : (cT / TT);
    const int r  = tid >> 3;
    const int jb = tid & 7;

    for (int tile = 0; tile < ntiles; tile++) {
        const int t0 = tile * TT;
        __syncthreads();
        for (int e = tid; e < TT * cHK; e += 256) {
            int tr = e >> 6, k = e & 63;
            KVs[tr * 65 + k] = Kb[base + (size_t)(t0 + tr) * rowStride + k];
        }
        __syncthreads();
        float acc[8] = {};
        #pragma unroll 16
        for (int k = 0; k < cHK; k++) {
            float qv = Qs[r * 65 + k];
            #pragma unroll
            for (int j = 0; j < 8; j++)
                acc[j] += qv * KVs[(jb + 8 * j) * 65 + k];
        }
        #pragma unroll
        for (int j = 0; j < 8; j++)
            sc[r * cT + t0 + jb + 8 * j] = acc[j] * 0.125f;
    }
    __syncthreads();

    {
        const int warp = tid >> 5, lane = tid & 31;
        float vals[16];
        for (int rr = 0; rr < 4; rr++) {
            const int row = warp * 4 + rr;
            const int sg  = s0 + row;
            float m = -1e30f;
            #pragma unroll
            for (int i = 0; i < 16; i++) {
                int t = lane + 32 * i;
                float vv = sc[row * cT + t];
                if (CAUSAL && t > sg) vv = -1e9f;
                vals[i] = vv;
                m = fmaxf(m, vv);
            }
            #pragma unroll
            for (int o = 16; o; o >>= 1) m = fmaxf(m, __shfl_xor_sync(0xffffffffu, m, o));
            float sum = 0.f;
            #pragma unroll
            for (int i = 0; i < 16; i++) { vals[i] = __expf(vals[i] - m); sum += vals[i]; }
            #pragma unroll
            for (int o = 16; o; o >>= 1) sum += __shfl_xor_sync(0xffffffffu, sum, o);
            const float inv = 1.f / sum;
            const size_t obase = ((size_t)(b * cH + h) * cS + sg) * cT;
            #pragma unroll
            for (int i = 0; i < 16; i++) {
                int t = lane + 32 * i;
                float p = vals[i] * inv;
                sc[row * cT + t] = p;
                attn_out[obase + t] = p;
            }
        }
    }
    __syncthreads();

    float cacc[8] = {};
    for (int tile = 0; tile < ntiles; tile++) {
        const int t0 = tile * TT;
        __syncthreads();
        for (int e = tid; e < TT * cHK; e += 256) {
            int tr = e >> 6, k = e & 63;
            KVs[tr * 65 + k] = Vb[base + (size_t)(t0 + tr) * rowStride + k];
        }
        __syncthreads();
        #pragma unroll 16
        for (int k = 0; k < TT; k++) {
            float a = sc[r * cT + t0 + k];
            #pragma unroll
            for (int j = 0; j < 8; j++)
                cacc[j] += a * KVs[k * 65 + jb + 8 * j];
        }
    }
    #pragma unroll
    for (int j = 0; j < 8; j++)
        ctx[base + (size_t)(s0 + r) * rowStride + jb + 8 * j] = cacc[j];
}

// ---------------- add-residual + layernorm ------------------------------------------
__global__ void add_ln_kernel(const float* __restrict__ a,
                              const float* __restrict__ res,
                              const float* __restrict__ g,
                              const float* __restrict__ be,
                              float* __restrict__ out)
{
    __shared__ float red[8];
    __shared__ float stat;
    const int row = blockIdx.x, tid = threadIdx.x;
    const size_t base = (size_t)row * cD;
    float v[4]; float s = 0.f;
    #pragma unroll
    for (int i = 0; i < 4; i++) {
        int c = tid + 256 * i;
        float t = a[base + c] + res[base + c];
        v[i] = t; s += t;
    }
    #pragma unroll
    for (int o = 16; o; o >>= 1) s += __shfl_xor_sync(0xffffffffu, s, o);
    if ((tid & 31) == 0) red[tid >> 5] = s;
    __syncthreads();
    if (tid == 0) { float t = 0; for (int i = 0; i < 8; i++) t += red[i]; stat = t * (1.f / cD); }
    __syncthreads();
    const float mu = stat;
    float s2 = 0.f;
    #pragma unroll
    for (int i = 0; i < 4; i++) { float d = v[i] - mu; s2 += d * d; }
    #pragma unroll
    for (int o = 16; o; o >>= 1) s2 += __shfl_xor_sync(0xffffffffu, s2, o);
    __syncthreads();
    if ((tid & 31) == 0) red[tid >> 5] = s2;
    __syncthreads();
    if (tid == 0) { float t = 0; for (int i = 0; i < 8; i++) t += red[i];
                    stat = rsqrtf(t * (1.f / cD) + 1e-6f); }
    __syncthreads();
    const float rstd = stat;
    #pragma unroll
    for (int i = 0; i < 4; i++) {
        int c = tid + 256 * i;
        out[base + c] = (v[i] - mu) * rstd * g[c] + be[c];
    }
}

// ---------------- launch ------------------------------------------------------------
extern "C" void kernel_launch(void* const* d_in, const int* in_sizes, int n_in,
                              void* d_out, int out_size)
{
    const float* x    = (const float*)d_in[0];
    const float* enc  = (const float*)d_in[1];
    const float* wq1  = (const float*)d_in[3];  const float* bq1 = (const float*)d_in[4];
    const float* wk1  = (const float*)d_in[5];  const float* bk1 = (const float*)d_in[6];
    const float* wv1  = (const float*)d_in[7];  const float* bv1 = (const float*)d_in[8];
    const float* wo1  = (const float*)d_in[9];  const float* bo1 = (const float*)d_in[10];
    const float* wq2  = (const float*)d_in[11]; const float* bq2 = (const float*)d_in[12];
    const float* wk2  = (const float*)d_in[13]; const float* bk2 = (const float*)d_in[14];
    const float* wv2  = (const float*)d_in[15]; const float* bv2 = (const float*)d_in[16];
    const float* wo2  = (const float*)d_in[17]; const float* bo2 = (const float*)d_in[18];
    const float* g1   = (const float*)d_in[19]; const float* be1 = (const float*)d_in[20];
    const float* g2   = (const float*)d_in[21]; const float* be2 = (const float*)d_in[22];
    const float* g3   = (const float*)d_in[23]; const float* be3 = (const float*)d_in[24];
    const float* wf1  = (const float*)d_in[25]; const float* bf1 = (const float*)d_in[26];
    const float* wf2  = (const float*)d_in[27]; const float* bf2 = (const float*)d_in[28];

    float* out   = (float*)d_out;
    float* attn1 = out + (size_t)cB * cS * cD;
    float* attn2 = attn1 + (size_t)cB * cH * cS * cS;

    float *q, *k, *v, *ctx, *tmp, *o1, *o2, *hb, *wt;
    cudaGetSymbolAddress((void**)&q,   g_q);
    cudaGetSymbolAddress((void**)&k,   g_k);
    cudaGetSymbolAddress((void**)&v,   g_v);
    cudaGetSymbolAddress((void**)&ctx, g_ctx);
    cudaGetSymbolAddress((void**)&tmp, g_tmp);
    cudaGetSymbolAddress((void**)&o1,  g_o1);
    cudaGetSymbolAddress((void**)&o2,  g_o2);
    cudaGetSymbolAddress((void**)&hb,  g_h);
    cudaGetSymbolAddress((void**)&wt,  g_wt);

    const size_t MEG = 1024 * 1024;
    float* wq1T = wt;            float* wk1T = wt + 1 * MEG;
    float* wv1T = wt + 2 * MEG;  float* wo1T = wt + 3 * MEG;
    float* wq2T = wt + 4 * MEG;  float* wk2T = wt + 5 * MEG;
    float* wv2T = wt + 6 * MEG;  float* wo2T = wt + 7 * MEG;
    float* wf1T = wt + 8 * MEG;  float* wf2T = wt + 12 * MEG;

    const int smemAttn = (SB * cT + SB * 65 + TT * 65) * (int)sizeof(float);
    cudaFuncSetAttribute(attn_kernel<1>, cudaFuncAttributeMaxDynamicSharedMemorySize, smemAttn);
    cudaFuncSetAttribute(attn_kernel<0>, cudaFuncAttributeMaxDynamicSharedMemorySize, smemAttn);
    cudaFuncSetAttribute(mma_gemm, cudaFuncAttributeMaxDynamicSharedMemorySize, MM_SMEM);

    // ---- transpose all weights (fp32) ----
    dim3 tb(32, 8);
    dim3 tg1(cD / 32, cD / 32);
    dim3 tgF(cF / 32, cD / 32);
    dim3 tgF2(cD / 32, cF / 32);
    transpose_kernel<<<tg1, tb>>>(wq1, wq1T, cD, cD);
    transpose_kernel<<<tg1, tb>>>(wk1, wk1T, cD, cD);
    transpose_kernel<<<tg1, tb>>>(wv1, wv1T, cD, cD);
    transpose_kernel<<<tg1, tb>>>(wo1, wo1T, cD, cD);
    transpose_kernel<<<tg1, tb>>>(wq2, wq2T, cD, cD);
    transpose_kernel<<<tg1, tb>>>(wk2, wk2T, cD, cD);
    transpose_kernel<<<tg1, tb>>>(wv2, wv2T, cD, cD);
    transpose_kernel<<<tg1, tb>>>(wo2, wo2T, cD, cD);
    transpose_kernel<<<tgF, tb>>>(wf1, wf1T, cD, cF);
    transpose_kernel<<<tgF2, tb>>>(wf2, wf2T, cF, cD);

    const int M = cB * cS;                      // 4096
    dim3 gP(cD / 128, M / 128);                 // (8, 32)
    dim3 gF1g(cF / 128, M / 128);               // (32, 32)
    dim3 gA(cS / SB, cH, cB);

    // ---- mha1 (self, causal) ----
    mma_gemm<<<gP, 256, MM_SMEM>>>(x, wq1T, bq1, q, cD, cD, 0);
    mma_gemm<<<gP, 256, MM_SMEM>>>(x, wk1T, bk1, k, cD, cD, 0);
    mma_gemm<<<gP, 256, MM_SMEM>>>(x, wv1T, bv1, v, cD, cD, 0);
    attn_kernel<1><<<gA, 256, smemAttn>>>(q, k, v, attn1, ctx);
    mma_gemm<<<gP, 256, MM_SMEM>>>(ctx, wo1T, bo1, tmp, cD, cD, 0);
    add_ln_kernel<<<M, 256>>>(tmp, x, g1, be1, o1);

    // ---- mha2 (cross) ----
    mma_gemm<<<gP, 256, MM_SMEM>>>(o1,  wq2T, bq2, q, cD, cD, 0);
    mma_gemm<<<gP, 256, MM_SMEM>>>(enc, wk2T, bk2, k, cD, cD, 0);
    mma_gemm<<<gP, 256, MM_SMEM>>>(enc, wv2T, bv2, v, cD, cD, 0);
    attn_kernel<0><<<gA, 256, smemAttn>>>(q, k, v, attn2, ctx);
    mma_gemm<<<gP, 256, MM_SMEM>>>(ctx, wo2T, bo2, tmp, cD, cD, 0);
    add_ln_kernel<<<M, 256>>>(tmp, o1, g2, be2, o2);

    // ---- ffn ----
    mma_gemm<<<gF1g, 256, MM_SMEM>>>(o2, wf1T, bf1, hb, cF, cD, 1);
    mma_gemm<<<gP, 256, MM_SMEM>>>(hb, wf2T, bf2, tmp, cD, cF, 0);
    add_ln_kernel<<<M, 256>>>(tmp, o2, g3, be3, out);
}

// round 8
// speedup vs baseline: 1.3527x; 1.0047x over previous
#include <cuda_runtime.h>
#include <cuda_bf16.h>
#include <cstdint>
#include <math.h>

// Problem constants
constexpr int cB = 8, cS = 512, cT = 512, cH = 16, cHK = 64, cD = 1024, cF = 4096;
constexpr int SB = 32;   // s-rows per attention block
constexpr int TT = 64;   // t-tile width

// ---------------- scratch (device globals; no allocation allowed) ----------------
__device__ float g_q  [(size_t)cB * cS * cD];
__device__ float g_k  [(size_t)cB * cS * cD];
__device__ float g_v  [(size_t)cB * cS * cD];
__device__ float g_ctx[(size_t)cB * cS * cD];
__device__ float g_tmp[(size_t)cB * cS * cD];
__device__ float g_o1 [(size_t)cB * cS * cD];
__device__ float g_o2 [(size_t)cB * cS * cD];
__device__ float g_h  [(size_t)cB * cS * cF];
// bf16 hi/lo pre-split buffers
__device__ __nv_bfloat16 g_wbh[(size_t)16 * 1024 * 1024];   // weights hi (transposed)
__device__ __nv_bfloat16 g_wbl[(size_t)16 * 1024 * 1024];   // weights lo
__device__ __nv_bfloat16 g_abh[(size_t)36 * 1024 * 1024];   // activations hi
__device__ __nv_bfloat16 g_abl[(size_t)36 * 1024 * 1024];   // activations lo

__device__ __forceinline__ uint32_t smem_u32(const void* p) {
    uint32_t a;
    asm("{ .reg .u64 t; cvta.to.shared.u64 t, %1; cvt.u32.u64 %0, t; }" : "=r"(a) : "l"(p));
    return a;
}

#define LDSM_X4(r0, r1, r2, r3, addr)                                             \
    asm volatile("ldmatrix.sync.aligned.m8n8.x4.shared.b16 {%0,%1,%2,%3}, [%4];"  \
                 : "=r"(r0), "=r"(r1), "=r"(r2), "=r"(r3) : "r"(addr))

#define MMA16816(d, a, b0, b1)                                                    \
    asm volatile("mma.sync.aligned.m16n8k16.row.col.f32.bf16.bf16.f32 "           \
                 "{%0,%1,%2,%3}, {%4,%5,%6,%7}, {%8,%9}, {%0,%1,%2,%3};"          \
                 : "+f"((d)[0]), "+f"((d)[1]), "+f"((d)[2]), "+f"((d)[3])         \
                 : "r"((a)[0]), "r"((a)[1]), "r"((a)[2]), "r"((a)[3]),            \
                   "r"(b0), "r"(b1))

// ---------------- elementwise fp32 -> bf16 hi/lo split ------------------------------
__global__ void split_kernel(const float* __restrict__ src,
                             __nv_bfloat16* __restrict__ dh,
                             __nv_bfloat16* __restrict__ dl, int n4)
{
    int i = blockIdx.x * blockDim.x + threadIdx.x;
    if (i >= n4) return;
    float4 v = ((const float4*)src)[i];
    __nv_bfloat162 h0, h1, l0, l1;
    h0.x = __float2bfloat16(v.x); h0.y = __float2bfloat16(v.y);
    h1.x = __float2bfloat16(v.z); h1.y = __float2bfloat16(v.w);
    l0.x = __float2bfloat16(v.x - __bfloat162float(h0.x));
    l0.y = __float2bfloat16(v.y - __bfloat162float(h0.y));
    l1.x = __float2bfloat16(v.z - __bfloat162float(h1.x));
    l1.y = __float2bfloat16(v.w - __bfloat162float(h1.y));
    ((__nv_bfloat162*)dh)[2 * i]     = h0;
    ((__nv_bfloat162*)dh)[2 * i + 1] = h1;
    ((__nv_bfloat162*)dl)[2 * i]     = l0;
    ((__nv_bfloat162*)dl)[2 * i + 1] = l1;
}

// ---------------- weight transpose + split: dst[c][r] = split(src[r][c]) -----------
__global__ void transpose_split_kernel(const float* __restrict__ src,
                                       __nv_bfloat16* __restrict__ dh,
                                       __nv_bfloat16* __restrict__ dl,
                                       int R, int Ccols)
{
    __shared__ float t[32][33];
    const int c0 = blockIdx.x * 32, r0 = blockIdx.y * 32;
    const int x = threadIdx.x, y = threadIdx.y;
    #pragma unroll
    for (int i = 0; i < 32; i += 8)
        t[y + i][x] = src[(size_t)(r0 + y + i) * Ccols + c0 + x];
    __syncthreads();
    #pragma unroll
    for (int i = 0; i < 32; i += 8) {
        float v = t[x][y + i];
        __nv_bfloat16 h = __float2bfloat16(v);
        size_t o = (size_t)(c0 + y + i) * R + r0 + x;
        dh[o] = h;
        dl[o] = __float2bfloat16(v - __bfloat162float(h));
    }
}

// ---------------- HMMA bf16 GEMM, operands pre-split --------------------------------
// C[M,N] = A[M,Kd] @ Bt[N,Kd]^T + bias[N], opt relu.
// BM=128, BN=128, BK=32, 256 thr (8 warps, 4x2), warp tile 32x64.
constexpr int LDT = 40;                     // bf16 elems per smem row (32 + 8 pad)
constexpr int TILE_B16 = 128 * LDT;         // per-tile bf16 elems
constexpr int MM_BUF = 4 * TILE_B16;        // Ah, Al, Bh, Bl per stage
constexpr int MM_SMEM = 2 * MM_BUF * 2;     // bytes: 81920

__global__ __launch_bounds__(256, 1)
void mma_gemm(const __nv_bfloat16* __restrict__ AH, const __nv_bfloat16* __restrict__ AL,
              const __nv_bfloat16* __restrict__ BH, const __nv_bfloat16* __restrict__ BL,
              const float* __restrict__ bias, float* __restrict__ C,
              int N, int Kd, int relu)
{
    extern __shared__ __nv_bfloat16 smb[];
    const int tid = threadIdx.x;
    const int lane = tid & 31, warp = tid >> 5;
    const int m0 = blockIdx.y * 128, n0 = blockIdx.x * 128;
    const int wm0 = (warp & 3) * 32, wn0 = (warp >> 2) * 64;

    __nv_bfloat16* Ah[2]; __nv_bfloat16* Al[2];
    __nv_bfloat16* Bh[2]; __nv_bfloat16* Bl[2];
    #pragma unroll
    for (int s = 0; s < 2; s++) {
        __nv_bfloat16* p = smb + s * MM_BUF;
        Ah[s] = p; Al[s] = p + TILE_B16; Bh[s] = p + 2 * TILE_B16; Bl[s] = p + 3 * TILE_B16;
    }

    // copy mapping: 512 uint4 chunks per 128x32 bf16 tile; 2 per thread
    int crow[2], ccol[2];
    #pragma unroll
    for (int i = 0; i < 2; i++) { int f = tid + 256 * i; crow[i] = f >> 2; ccol[i] = (f & 3) * 8; }

    uint4 rah[2], ral[2], rbh[2], rbl[2];
    auto load_global = [&](int c) {
        #pragma unroll
        for (int i = 0; i < 2; i++) {
            size_t ao = (size_t)(m0 + crow[i]) * Kd + c * 32 + ccol[i];
            size_t bo = (size_t)(n0 + crow[i]) * Kd + c * 32 + ccol[i];
            rah[i] = *(const uint4*)(AH + ao);
            ral[i] = *(const uint4*)(AL + ao);
            rbh[i] = *(const uint4*)(BH + bo);
            rbl[i] = *(const uint4*)(BL + bo);
        }
    };
    auto store_smem = [&](int s) {
        #pragma unroll
        for (int i = 0; i < 2; i++) {
            int so = crow[i] * LDT + ccol[i];
            *(uint4*)(Ah[s] + so) = rah[i];
            *(uint4*)(Al[s] + so) = ral[i];
            *(uint4*)(Bh[s] + so) = rbh[i];
            *(uint4*)(Bl[s] + so) = rbl[i];
        }
    };

    float acc[2][8][4] = {};

    // ldmatrix address offsets (elements)
    const int aoff = (wm0 + (lane & 15)) * LDT + ((lane >> 4) << 3);        // + mf*16*LDT
    const int boff = (wn0 + (((lane >> 4) & 1) << 3) + (lane & 7)) * LDT
                   + (((lane >> 3) & 1) << 3);                              // + j*8*LDT (+kk)

    const int NC = Kd >> 5;
    load_global(0);
    store_smem(0);
    __syncthreads();

    for (int c = 0; c < NC; c++) {
        const int buf = c & 1;
        if (c + 1 < NC) load_global(c + 1);

        const uint32_t sAh = smem_u32(Ah[buf]), sAl = smem_u32(Al[buf]);
        const uint32_t sBh = smem_u32(Bh[buf]), sBl = smem_u32(Bl[buf]);
        #pragma unroll
        for (int kk = 0; kk < 32; kk += 16) {
            uint32_t ah[2][4], al[2][4];
            #pragma unroll
            for (int mf = 0; mf < 2; mf++) {
                uint32_t adr = (uint32_t)((aoff + mf * 16 * LDT + kk) * 2);
                LDSM_X4(ah[mf][0], ah[mf][1], ah[mf][2], ah[mf][3], sAh + adr);
                LDSM_X4(al[mf][0], al[mf][1], al[mf][2], al[mf][3], sAl + adr);
            }
            #pragma unroll
            for (int j = 0; j < 8; j += 2) {
                uint32_t bh[4], bl[4];
                uint32_t adr = (uint32_t)((boff + j * 8 * LDT + kk) * 2);
                LDSM_X4(bh[0], bh[1], bh[2], bh[3], sBh + adr);
                LDSM_X4(bl[0], bl[1], bl[2], bl[3], sBl + adr);
                #pragma unroll
                for (int mf = 0; mf < 2; mf++) {
                    MMA16816(acc[mf][j],     ah[mf], bh[0], bh[1]);
                    MMA16816(acc[mf][j],     al[mf], bh[0], bh[1]);
                    MMA16816(acc[mf][j],     ah[mf], bl[0], bl[1]);
                    MMA16816(acc[mf][j + 1], ah[mf], bh[2], bh[3]);
                    MMA16816(acc[mf][j + 1], al[mf], bh[2], bh[3]);
                    MMA16816(acc[mf][j + 1], ah[mf], bl[2], bl[3]);
                }
            }
        }
        if (c + 1 < NC) store_smem(buf ^ 1);
        __syncthreads();
    }

    // epilogue
    #pragma unroll
    for (int mf = 0; mf < 2; mf++) {
        const int row = m0 + wm0 + mf * 16 + (lane >> 2);
        #pragma unroll
        for (int j = 0; j < 8; j++) {
            const int col = n0 + wn0 + j * 8 + (lane & 3) * 2;
            const float b0 = bias[col], b1 = bias[col + 1];
            float2 v0 = { acc[mf][j][0] + b0, acc[mf][j][1] + b1 };
            float2 v1 = { acc[mf][j][2] + b0, acc[mf][j][3] + b1 };
            if (relu) {
                v0.x = fmaxf(v0.x, 0.f); v0.y = fmaxf(v0.y, 0.f);
                v1.x = fmaxf(v1.x, 0.f); v1.y = fmaxf(v1.y, 0.f);
            }
            *(float2*)&C[(size_t)row * N + col]       = v0;
            *(float2*)&C[(size_t)(row + 8) * N + col] = v1;
        }
    }
}

// ---------------- fused attention: scores -> softmax -> attn write -> ctx ----------
template <int CAUSAL>
__global__ void attn_kernel(const float* __restrict__ Q,
                            const float* __restrict__ Kb,
                            const float* __restrict__ Vb,
                            float* __restrict__ attn_out,
                            float* __restrict__ ctx)
{
    extern __shared__ float sm[];
    float* sc  = sm;                    // [SB][cT]
    float* Qs  = sm + SB * cT;          // [SB][65]
    float* KVs = Qs + SB * 65;          // [TT][65]

    const int tid = threadIdx.x;
    const int s0  = blockIdx.x * SB;
    const int h   = blockIdx.y;
    const int b   = blockIdx.z;
    const size_t base = ((size_t)(b * cS) * cH + h) * cHK;
    const int rowStride = cH * cHK;

    for (int e = tid; e < SB * cHK; e += 256) {
        int r = e >> 6, k = e & 63;
        Qs[r * 65 + k] = Q[base + (size_t)(s0 + r) * rowStride + k];
    }

    const int ntiles = CAUSAL ? ((s0 + SB - 1) / TT + 1) : (cT / TT);
    const int r  = tid >> 3;
    const int jb = tid & 7;

    for (int tile = 0; tile < ntiles; tile++) {
        const int t0 = tile * TT;
        __syncthreads();
        for (int e = tid; e < TT * cHK; e += 256) {
            int tr = e >> 6, k = e & 63;
            KVs[tr * 65 + k] = Kb[base + (size_t)(t0 + tr) * rowStride + k];
        }
        __syncthreads();
        float acc[8] = {};
        #pragma unroll 16
        for (int k = 0; k < cHK; k++) {
            float qv = Qs[r * 65 + k];
            #pragma unroll
            for (int j = 0; j < 8; j++)
                acc[j] += qv * KVs[(jb + 8 * j) * 65 + k];
        }
        #pragma unroll
        for (int j = 0; j < 8; j++)
            sc[r * cT + t0 + jb + 8 * j] = acc[j] * 0.125f;
    }
    __syncthreads();

    {
        const int warp = tid >> 5, lane = tid & 31;
        float vals[16];
        for (int rr = 0; rr < 4; rr++) {
            const int row = warp * 4 + rr;
            const int sg  = s0 + row;
            float m = -1e30f;
            #pragma unroll
            for (int i = 0; i < 16; i++) {
                int t = lane + 32 * i;
                float vv = sc[row * cT + t];
                if (CAUSAL && t > sg) vv = -1e9f;
                vals[i] = vv;
                m = fmaxf(m, vv);
            }
            #pragma unroll
            for (int o = 16; o; o >>= 1) m = fmaxf(m, __shfl_xor_sync(0xffffffffu, m, o));
            float sum = 0.f;
            #pragma unroll
            for (int i = 0; i < 16; i++) { vals[i] = __expf(vals[i] - m); sum += vals[i]; }
            #pragma unroll
            for (int o = 16; o; o >>= 1) sum += __shfl_xor_sync(0xffffffffu, sum, o);
            const float inv = 1.f / sum;
            const size_t obase = ((size_t)(b * cH + h) * cS + sg) * cT;
            #pragma unroll
            for (int i = 0; i < 16; i++) {
                int t = lane + 32 * i;
                float p = vals[i] * inv;
                sc[row * cT + t] = p;
                attn_out[obase + t] = p;
            }
        }
    }
    __syncthreads();

    float cacc[8] = {};
    for (int tile = 0; tile < ntiles; tile++) {
        const int t0 = tile * TT;
        __syncthreads();
        for (int e = tid; e < TT * cHK; e += 256) {
            int tr = e >> 6, k = e & 63;
            KVs[tr * 65 + k] = Vb[base + (size_t)(t0 + tr) * rowStride + k];
        }
        __syncthreads();
        #pragma unroll 16
        for (int k = 0; k < TT; k++) {
            float a = sc[r * cT + t0 + k];
            #pragma unroll
            for (int j = 0; j < 8; j++)
                cacc[j] += a * KVs[k * 65 + jb + 8 * j];
        }
    }
    #pragma unroll
    for (int j = 0; j < 8; j++)
        ctx[base + (size_t)(s0 + r) * rowStride + jb + 8 * j] = cacc[j];
}

// ---------------- add-residual + layernorm ------------------------------------------
__global__ void add_ln_kernel(const float* __restrict__ a,
                              const float* __restrict__ res,
                              const float* __restrict__ g,
                              const float* __restrict__ be,
                              float* __restrict__ out)
{
    __shared__ float red[8];
    __shared__ float stat;
    const int row = blockIdx.x, tid = threadIdx.x;
    const size_t base = (size_t)row * cD;
    float v[4]; float s = 0.f;
    #pragma unroll
    for (int i = 0; i < 4; i++) {
        int c = tid + 256 * i;
        float t = a[base + c] + res[base + c];
        v[i] = t; s += t;
    }
    #pragma unroll
    for (int o = 16; o; o >>= 1) s += __shfl_xor_sync(0xffffffffu, s, o);
    if ((tid & 31) == 0) red[tid >> 5] = s;
    __syncthreads();
    if (tid == 0) { float t = 0; for (int i = 0; i < 8; i++) t += red[i]; stat = t * (1.f / cD); }
    __syncthreads();
    const float mu = stat;
    float s2 = 0.f;
    #pragma unroll
    for (int i = 0; i < 4; i++) { float d = v[i] - mu; s2 += d * d; }
    #pragma unroll
    for (int o = 16; o; o >>= 1) s2 += __shfl_xor_sync(0xffffffffu, s2, o);
    __syncthreads();
    if ((tid & 31) == 0) red[tid >> 5] = s2;
    __syncthreads();
    if (tid == 0) { float t = 0; for (int i = 0; i < 8; i++) t += red[i];
                    stat = rsqrtf(t * (1.f / cD) + 1e-6f); }
    __syncthreads();
    const float rstd = stat;
    #pragma unroll
    for (int i = 0; i < 4; i++) {
        int c = tid + 256 * i;
        out[base + c] = (v[i] - mu) * rstd * g[c] + be[c];
    }
}

// ---------------- launch ------------------------------------------------------------
extern "C" void kernel_launch(void* const* d_in, const int* in_sizes, int n_in,
                              void* d_out, int out_size)
{
    const float* x    = (const float*)d_in[0];
    const float* enc  = (const float*)d_in[1];
    const float* wq1  = (const float*)d_in[3];  const float* bq1 = (const float*)d_in[4];
    const float* wk1  = (const float*)d_in[5];  const float* bk1 = (const float*)d_in[6];
    const float* wv1  = (const float*)d_in[7];  const float* bv1 = (const float*)d_in[8];
    const float* wo1  = (const float*)d_in[9];  const float* bo1 = (const float*)d_in[10];
    const float* wq2  = (const float*)d_in[11]; const float* bq2 = (const float*)d_in[12];
    const float* wk2  = (const float*)d_in[13]; const float* bk2 = (const float*)d_in[14];
    const float* wv2  = (const float*)d_in[15]; const float* bv2 = (const float*)d_in[16];
    const float* wo2  = (const float*)d_in[17]; const float* bo2 = (const float*)d_in[18];
    const float* g1   = (const float*)d_in[19]; const float* be1 = (const float*)d_in[20];
    const float* g2   = (const float*)d_in[21]; const float* be2 = (const float*)d_in[22];
    const float* g3   = (const float*)d_in[23]; const float* be3 = (const float*)d_in[24];
    const float* wf1  = (const float*)d_in[25]; const float* bf1 = (const float*)d_in[26];
    const float* wf2  = (const float*)d_in[27]; const float* bf2 = (const float*)d_in[28];

    float* out   = (float*)d_out;
    float* attn1 = out + (size_t)cB * cS * cD;
    float* attn2 = attn1 + (size_t)cB * cH * cS * cS;

    float *q, *k, *v, *ctx, *tmp, *o1, *o2, *hb;
    __nv_bfloat16 *wbh, *wbl, *abh, *abl;
    cudaGetSymbolAddress((void**)&q,   g_q);
    cudaGetSymbolAddress((void**)&k,   g_k);
    cudaGetSymbolAddress((void**)&v,   g_v);
    cudaGetSymbolAddress((void**)&ctx, g_ctx);
    cudaGetSymbolAddress((void**)&tmp, g_tmp);
    cudaGetSymbolAddress((void**)&o1,  g_o1);
    cudaGetSymbolAddress((void**)&o2,  g_o2);
    cudaGetSymbolAddress((void**)&hb,  g_h);
    cudaGetSymbolAddress((void**)&wbh, g_wbh);
    cudaGetSymbolAddress((void**)&wbl, g_wbl);
    cudaGetSymbolAddress((void**)&abh, g_abh);
    cudaGetSymbolAddress((void**)&abl, g_abl);

    const size_t MEG = 1024 * 1024;
    // weight offsets (elements)
    __nv_bfloat16 *q1H = wbh + 0*MEG, *q1L = wbl + 0*MEG;
    __nv_bfloat16 *k1H = wbh + 1*MEG, *k1L = wbl + 1*MEG;
    __nv_bfloat16 *v1H = wbh + 2*MEG, *v1L = wbl + 2*MEG;
    __nv_bfloat16 *o1H = wbh + 3*MEG, *o1L = wbl + 3*MEG;
    __nv_bfloat16 *q2H = wbh + 4*MEG, *q2L = wbl + 4*MEG;
    __nv_bfloat16 *k2H = wbh + 5*MEG, *k2L = wbl + 5*MEG;
    __nv_bfloat16 *v2H = wbh + 6*MEG, *v2L = wbl + 6*MEG;
    __nv_bfloat16 *o2H = wbh + 7*MEG, *o2L = wbl + 7*MEG;
    __nv_bfloat16 *f1H = wbh + 8*MEG, *f1L = wbl + 8*MEG;
    __nv_bfloat16 *f2H = wbh + 12*MEG, *f2L = wbl + 12*MEG;
    // activation offsets
    const size_t ACT = (size_t)cB * cS * cD;            // 4M
    __nv_bfloat16 *xH   = abh + 0*ACT,  *xL   = abl + 0*ACT;
    __nv_bfloat16 *encH = abh + 1*ACT,  *encL = abl + 1*ACT;
    __nv_bfloat16 *ctxH = abh + 2*ACT,  *ctxL = abl + 2*ACT;
    __nv_bfloat16 *oa1H = abh + 3*ACT,  *oa1L = abl + 3*ACT;
    __nv_bfloat16 *oa2H = abh + 4*ACT,  *oa2L = abl + 4*ACT;
    __nv_bfloat16 *hbH  = abh + 5*ACT,  *hbL  = abl + 5*ACT;   // 16M elems

    const int smemAttn = (SB * cT + SB * 65 + TT * 65) * (int)sizeof(float);
    cudaFuncSetAttribute(attn_kernel<1>, cudaFuncAttributeMaxDynamicSharedMemorySize, smemAttn);
    cudaFuncSetAttribute(attn_kernel<0>, cudaFuncAttributeMaxDynamicSharedMemorySize, smemAttn);
    cudaFuncSetAttribute(mma_gemm, cudaFuncAttributeMaxDynamicSharedMemorySize, MM_SMEM);

    // ---- transpose + split weights ----
    dim3 tb(32, 8);
    dim3 tg1(cD / 32, cD / 32);
    dim3 tgF(cF / 32, cD / 32);
    dim3 tgF2(cD / 32, cF / 32);
    transpose_split_kernel<<<tg1, tb>>>(wq1, q1H, q1L, cD, cD);
    transpose_split_kernel<<<tg1, tb>>>(wk1, k1H, k1L, cD, cD);
    transpose_split_kernel<<<tg1, tb>>>(wv1, v1H, v1L, cD, cD);
    transpose_split_kernel<<<tg1, tb>>>(wo1, o1H, o1L, cD, cD);
    transpose_split_kernel<<<tg1, tb>>>(wq2, q2H, q2L, cD, cD);
    transpose_split_kernel<<<tg1, tb>>>(wk2, k2H, k2L, cD, cD);
    transpose_split_kernel<<<tg1, tb>>>(wv2, v2H, v2L, cD, cD);
    transpose_split_kernel<<<tg1, tb>>>(wo2, o2H, o2L, cD, cD);
    transpose_split_kernel<<<tgF, tb>>>(wf1, f1H, f1L, cD, cF);
    transpose_split_kernel<<<tgF2, tb>>>(wf2, f2H, f2L, cF, cD);

    const int M = cB * cS;                      // 4096
    const int N4 = (int)(ACT / 4);              // 1M float4 per 4M-elem act
    const int N4h = N4 * 4;                     // hb: 16M elems
    dim3 gP(cD / 128, M / 128);                 // (8, 32)
    dim3 gF1g(cF / 128, M / 128);               // (32, 32)
    dim3 gA(cS / SB, cH, cB);

    // ---- input splits ----
    split_kernel<<<N4 / 256, 256>>>(x,   xH,   xL,   N4);
    split_kernel<<<N4 / 256, 256>>>(enc, encH, encL, N4);

    // ---- mha1 (self, causal) ----
    mma_gemm<<<gP, 256, MM_SMEM>>>(xH, xL, q1H, q1L, bq1, q, cD, cD, 0);
    mma_gemm<<<gP, 256, MM_SMEM>>>(xH, xL, k1H, k1L, bk1, k, cD, cD, 0);
    mma_gemm<<<gP, 256, MM_SMEM>>>(xH, xL, v1H, v1L, bv1, v, cD, cD, 0);
    attn_kernel<1><<<gA, 256, smemAttn>>>(q, k, v, attn1, ctx);
    split_kernel<<<N4 / 256, 256>>>(ctx, ctxH, ctxL, N4);
    mma_gemm<<<gP, 256, MM_SMEM>>>(ctxH, ctxL, o1H, o1L, bo1, tmp, cD, cD, 0);
    add_ln_kernel<<<M, 256>>>(tmp, x, g1, be1, o1);
    split_kernel<<<N4 / 256, 256>>>(o1, oa1H, oa1L, N4);

    // ---- mha2 (cross) ----
    mma_gemm<<<gP, 256, MM_SMEM>>>(oa1H, oa1L, q2H, q2L, bq2, q, cD, cD, 0);
    mma_gemm<<<gP, 256, MM_SMEM>>>(encH, encL, k2H, k2L, bk2, k, cD, cD, 0);
    mma_gemm<<<gP, 256, MM_SMEM>>>(encH, encL, v2H, v2L, bv2, v, cD, cD, 0);
    attn_kernel<0><<<gA, 256, smemAttn>>>(q, k, v, attn2, ctx);
    split_kernel<<<N4 / 256, 256>>>(ctx, ctxH, ctxL, N4);
    mma_gemm<<<gP, 256, MM_SMEM>>>(ctxH, ctxL, o2H, o2L, bo2, tmp, cD, cD, 0);
    add_ln_kernel<<<M, 256>>>(tmp, o1, g2, be2, o2);
    split_kernel<<<N4 / 256, 256>>>(o2, oa2H, oa2L, N4);

    // ---- ffn ----
    mma_gemm<<<gF1g, 256, MM_SMEM>>>(oa2H, oa2L, f1H, f1L, bf1, hb, cF, cD, 1);
    split_kernel<<<N4h / 256, 256>>>(hb, hbH, hbL, N4h);
    mma_gemm<<<gP, 256, MM_SMEM>>>(hbH, hbL, f2H, f2L, bf2, tmp, cD, cF, 0);
    add_ln_kernel<<<M, 256>>>(tmp, o2, g3, be3, out);
}

// round 13
// speedup vs baseline: 1.6743x; 1.2378x over previous
#include <cuda_runtime.h>
#include <cuda_bf16.h>
#include <cstdint>
#include <math.h>

// Problem constants
constexpr int cB = 8, cS = 512, cT = 512, cH = 16, cHK = 64, cD = 1024, cF = 4096;
constexpr int SB = 32;   // s-rows per attention block
constexpr int TT = 64;   // t-tile width

// ---------------- scratch (device globals; no allocation allowed) ----------------
__device__ float g_q  [(size_t)cB * cS * cD];
__device__ float g_k  [(size_t)cB * cS * cD];
__device__ float g_v  [(size_t)cB * cS * cD];
__device__ float g_ctx[(size_t)cB * cS * cD];
__device__ float g_tmp[(size_t)cB * cS * cD];
__device__ float g_o1 [(size_t)cB * cS * cD];
__device__ float g_o2 [(size_t)cB * cS * cD];
__device__ float g_h  [(size_t)cB * cS * cF];
// bf16 hi/lo pre-split buffers
__device__ __nv_bfloat16 g_wbh[(size_t)16 * 1024 * 1024];   // weights hi (transposed)
__device__ __nv_bfloat16 g_wbl[(size_t)16 * 1024 * 1024];   // weights lo
__device__ __nv_bfloat16 g_abh[(size_t)36 * 1024 * 1024];   // activations hi
__device__ __nv_bfloat16 g_abl[(size_t)36 * 1024 * 1024];   // activations lo

__device__ __forceinline__ uint32_t smem_u32(const void* p) {
    uint32_t a;
    asm("{ .reg .u64 t; cvta.to.shared.u64 t, %1; cvt.u32.u64 %0, t; }" : "=r"(a) : "l"(p));
    return a;
}

#define LDSM_X4(r0, r1, r2, r3, addr)                                             \
    asm volatile("ldmatrix.sync.aligned.m8n8.x4.shared.b16 {%0,%1,%2,%3}, [%4];"  \
                 : "=r"(r0), "=r"(r1), "=r"(r2), "=r"(r3) : "r"(addr))

#define MMA16816(d, a, b0, b1)                                                    \
    asm volatile("mma.sync.aligned.m16n8k16.row.col.f32.bf16.bf16.f32 "           \
                 "{%0,%1,%2,%3}, {%4,%5,%6,%7}, {%8,%9}, {%0,%1,%2,%3};"          \
                 : "+f"((d)[0]), "+f"((d)[1]), "+f"((d)[2]), "+f"((d)[3])         \
                 : "r"((a)[0]), "r"((a)[1]), "r"((a)[2]), "r"((a)[3]),            \
                   "r"(b0), "r"(b1))

// ---------------- elementwise fp32 -> bf16 hi/lo split ------------------------------
__global__ void split_kernel(const float* __restrict__ src,
                             __nv_bfloat16* __restrict__ dh,
                             __nv_bfloat16* __restrict__ dl, int n4)
{
    int i = blockIdx.x * blockDim.x + threadIdx.x;
    if (i >= n4) return;
    float4 v = ((const float4*)src)[i];
    __nv_bfloat162 h0, h1, l0, l1;
    h0.x = __float2bfloat16(v.x); h0.y = __float2bfloat16(v.y);
    h1.x = __float2bfloat16(v.z); h1.y = __float2bfloat16(v.w);
    l0.x = __float2bfloat16(v.x - __bfloat162float(h0.x));
    l0.y = __float2bfloat16(v.y - __bfloat162float(h0.y));
    l1.x = __float2bfloat16(v.z - __bfloat162float(h1.x));
    l1.y = __float2bfloat16(v.w - __bfloat162float(h1.y));
    ((__nv_bfloat162*)dh)[2 * i]     = h0;
    ((__nv_bfloat162*)dh)[2 * i + 1] = h1;
    ((__nv_bfloat162*)dl)[2 * i]     = l0;
    ((__nv_bfloat162*)dl)[2 * i + 1] = l1;
}

// ---------------- weight transpose + split: dst[c][r] = split(src[r][c]) -----------
__global__ void transpose_split_kernel(const float* __restrict__ src,
                                       __nv_bfloat16* __restrict__ dh,
                                       __nv_bfloat16* __restrict__ dl,
                                       int R, int Ccols)
{
    __shared__ float t[32][33];
    const int c0 = blockIdx.x * 32, r0 = blockIdx.y * 32;
    const int x = threadIdx.x, y = threadIdx.y;
    #pragma unroll
    for (int i = 0; i < 32; i += 8)
        t[y + i][x] = src[(size_t)(r0 + y + i) * Ccols + c0 + x];
    __syncthreads();
    #pragma unroll
    for (int i = 0; i < 32; i += 8) {
        float v = t[x][y + i];
        __nv_bfloat16 h = __float2bfloat16(v);
        size_t o = (size_t)(c0 + y + i) * R + r0 + x;
        dh[o] = h;
        dl[o] = __float2bfloat16(v - __bfloat162float(h));
    }
}

// ---------------- HMMA bf16 GEMM, operands pre-split --------------------------------
// C[M,N] = A[M,Kd] @ Bt[N,Kd]^T + bias[N], opt relu.
// BM=128, BN=128, BK=32, 256 thr (8 warps, 4x2), warp tile 32x64.
constexpr int LDT = 40;                     // bf16 elems per smem row (32 + 8 pad)
constexpr int TILE_B16 = 128 * LDT;         // per-tile bf16 elems
constexpr int MM_BUF = 4 * TILE_B16;        // Ah, Al, Bh, Bl per stage
constexpr int MM_SMEM = 2 * MM_BUF * 2;     // bytes: 81920

__global__ __launch_bounds__(256, 2)
void mma_gemm(const __nv_bfloat16* __restrict__ AH, const __nv_bfloat16* __restrict__ AL,
              const __nv_bfloat16* __restrict__ BH, const __nv_bfloat16* __restrict__ BL,
              const float* __restrict__ bias, float* __restrict__ C,
              int N, int Kd, int relu)
{
    extern __shared__ __nv_bfloat16 smb[];
    const int tid = threadIdx.x;
    const int lane = tid & 31, warp = tid >> 5;
    const int m0 = blockIdx.y * 128, n0 = blockIdx.x * 128;
    const int wm0 = (warp & 3) * 32, wn0 = (warp >> 2) * 64;

    __nv_bfloat16* Ah[2]; __nv_bfloat16* Al[2];
    __nv_bfloat16* Bh[2]; __nv_bfloat16* Bl[2];
    #pragma unroll
    for (int s = 0; s < 2; s++) {
        __nv_bfloat16* p = smb + s * MM_BUF;
        Ah[s] = p; Al[s] = p + TILE_B16; Bh[s] = p + 2 * TILE_B16; Bl[s] = p + 3 * TILE_B16;
    }

    // copy mapping: 512 uint4 chunks per 128x32 bf16 tile; 2 per thread
    int crow[2], ccol[2];
    #pragma unroll
    for (int i = 0; i < 2; i++) { int f = tid + 256 * i; crow[i] = f >> 2; ccol[i] = (f & 3) * 8; }

    uint4 rah[2], ral[2], rbh[2], rbl[2];
    auto load_global = [&](int c) {
        #pragma unroll
        for (int i = 0; i < 2; i++) {
            size_t ao = (size_t)(m0 + crow[i]) * Kd + c * 32 + ccol[i];
            size_t bo = (size_t)(n0 + crow[i]) * Kd + c * 32 + ccol[i];
            rah[i] = *(const uint4*)(AH + ao);
            ral[i] = *(const uint4*)(AL + ao);
            rbh[i] = *(const uint4*)(BH + bo);
            rbl[i] = *(const uint4*)(BL + bo);
        }
    };
    auto store_smem = [&](int s) {
        #pragma unroll
        for (int i = 0; i < 2; i++) {
            int so = crow[i] * LDT + ccol[i];
            *(uint4*)(Ah[s] + so) = rah[i];
            *(uint4*)(Al[s] + so) = ral[i];
            *(uint4*)(Bh[s] + so) = rbh[i];
            *(uint4*)(Bl[s] + so) = rbl[i];
        }
    };

    float acc[2][8][4] = {};

    // ldmatrix address offsets (elements)
    const int aoff = (wm0 + (lane & 15)) * LDT + ((lane >> 4) << 3);        // + mf*16*LDT
    const int boff = (wn0 + (((lane >> 4) & 1) << 3) + (lane & 7)) * LDT
                   + (((lane >> 3) & 1) << 3);                              // + jp*16*LDT (+kk)

    const int NC = Kd >> 5;
    load_global(0);
    store_smem(0);
    __syncthreads();

    for (int c = 0; c < NC; c++) {
        const int buf = c & 1;
        if (c + 1 < NC) load_global(c + 1);

        const uint32_t sAh = smem_u32(Ah[buf]), sAl = smem_u32(Al[buf]);
        const uint32_t sBh = smem_u32(Bh[buf]), sBl = smem_u32(Bl[buf]);
        #pragma unroll
        for (int kk = 0; kk < 32; kk += 16) {
            uint32_t ah[2][4], al[2][4];
            #pragma unroll
            for (int mf = 0; mf < 2; mf++) {
                uint32_t adr = (uint32_t)((aoff + mf * 16 * LDT + kk) * 2);
                LDSM_X4(ah[mf][0], ah[mf][1], ah[mf][2], ah[mf][3], sAh + adr);
                LDSM_X4(al[mf][0], al[mf][1], al[mf][2], al[mf][3], sAl + adr);
            }
            #pragma unroll
            for (int jp = 0; jp < 4; jp++) {
                uint32_t bh[4], bl[4];
                uint32_t adr = (uint32_t)((boff + jp * 16 * LDT + kk) * 2);
                LDSM_X4(bh[0], bh[1], bh[2], bh[3], sBh + adr);
                LDSM_X4(bl[0], bl[1], bl[2], bl[3], sBl + adr);
                const int j0 = 2 * jp, j1 = 2 * jp + 1;
                // term-major: same-accumulator ops spaced 4 issues apart.
                // Per-accumulator order stays hh, lh, hl (bitwise-identical sums).
                MMA16816(acc[0][j0], ah[0], bh[0], bh[1]);
                MMA16816(acc[0][j1], ah[0], bh[2], bh[3]);
                MMA16816(acc[1][j0], ah[1], bh[0], bh[1]);
                MMA16816(acc[1][j1], ah[1], bh[2], bh[3]);
                MMA16816(acc[0][j0], al[0], bh[0], bh[1]);
                MMA16816(acc[0][j1], al[0], bh[2], bh[3]);
                MMA16816(acc[1][j0], al[1], bh[0], bh[1]);
                MMA16816(acc[1][j1], al[1], bh[2], bh[3]);
                MMA16816(acc[0][j0], ah[0], bl[0], bl[1]);
                MMA16816(acc[0][j1], ah[0], bl[2], bl[3]);
                MMA16816(acc[1][j0], ah[1], bl[0], bl[1]);
                MMA16816(acc[1][j1], ah[1], bl[2], bl[3]);
            }
        }
        if (c + 1 < NC) store_smem(buf ^ 1);
        __syncthreads();
    }

    // epilogue
    #pragma unroll
    for (int mf = 0; mf < 2; mf++) {
        const int row = m0 + wm0 + mf * 16 + (lane >> 2);
        #pragma unroll
        for (int j = 0; j < 8; j++) {
            const int col = n0 + wn0 + j * 8 + (lane & 3) * 2;
            const float b0 = bias[col], b1 = bias[col + 1];
            float2 v0 = { acc[mf][j][0] + b0, acc[mf][j][1] + b1 };
            float2 v1 = { acc[mf][j][2] + b0, acc[mf][j][3] + b1 };
            if (relu) {
                v0.x = fmaxf(v0.x, 0.f); v0.y = fmaxf(v0.y, 0.f);
                v1.x = fmaxf(v1.x, 0.f); v1.y = fmaxf(v1.y, 0.f);
            }
            *(float2*)&C[(size_t)row * N + col]       = v0;
            *(float2*)&C[(size_t)(row + 8) * N + col] = v1;
        }
    }
}

// ---------------- fused attention: scores -> softmax -> attn write -> ctx ----------
// Thread mapping: 2 rows x 4 cols per thread (rp = tid>>4, cg = tid&15).
// Each output element keeps the identical sequential k-summation as before;
// only thread ownership changes -> results are bit-identical.
template <int CAUSAL>
__global__ void attn_kernel(const float* __restrict__ Q,
                            const float* __restrict__ Kb,
                            const float* __restrict__ Vb,
                            float* __restrict__ attn_out,
                            float* __restrict__ ctx)
{
    extern __shared__ float sm[];
    float* sc  = sm;                    // [SB][cT]
    float* Qs  = sm + SB * cT;          // [SB][65]
    float* KVs = Qs + SB * 65;          // [TT][65]

    const int tid = threadIdx.x;
    const int s0  = blockIdx.x * SB;
    const int h   = blockIdx.y;
    const int b   = blockIdx.z;
    const size_t base = ((size_t)(b * cS) * cH + h) * cHK;
    const int rowStride = cH * cHK;

    for (int e = tid; e < SB * cHK; e += 256) {
        int r = e >> 6, k = e & 63;
        Qs[r * 65 + k] = Q[base + (size_t)(s0 + r) * rowStride + k];
    }

    const int ntiles = CAUSAL ? ((s0 + SB - 1) / TT + 1) : (cT / TT);
    const int rp = tid >> 4;            // 0..15
    const int cg = tid & 15;            // 0..15
    const int r0 = 2 * rp, r1 = 2 * rp + 1;

    // ---- scores: each thread 2 rows x 4 cols (cols cg + 16*j) ----
    for (int tile = 0; tile < ntiles; tile++) {
        const int t0 = tile * TT;
        __syncthreads();
        for (int e = tid; e < TT * cHK; e += 256) {
            int tr = e >> 6, k = e & 63;
            KVs[tr * 65 + k] = Kb[base + (size_t)(t0 + tr) * rowStride + k];
        }
        __syncthreads();
        float acc2[2][4] = {};
        #pragma unroll 16
        for (int k = 0; k < cHK; k++) {
            float q0 = Qs[r0 * 65 + k];
            float q1 = Qs[r1 * 65 + k];
            #pragma unroll
            for (int j = 0; j < 4; j++) {
                float kv = KVs[(cg + 16 * j) * 65 + k];
                acc2[0][j] += q0 * kv;
                acc2[1][j] += q1 * kv;
            }
        }
        #pragma unroll
        for (int j = 0; j < 4; j++) {
            sc[r0 * cT + t0 + cg + 16 * j] = acc2[0][j] * 0.125f;
            sc[r1 * cT + t0 + cg + 16 * j] = acc2[1][j] * 0.125f;
        }
    }
    __syncthreads();

    // ---- softmax + attn write (unchanged) ----
    {
        const int warp = tid >> 5, lane = tid & 31;
        float vals[16];
        for (int rr = 0; rr < 4; rr++) {
            const int row = warp * 4 + rr;
            const int sg  = s0 + row;
            float m = -1e30f;
            #pragma unroll
            for (int i = 0; i < 16; i++) {
                int t = lane + 32 * i;
                float vv = sc[row * cT + t];
                if (CAUSAL && t > sg) vv = -1e9f;
                vals[i] = vv;
                m = fmaxf(m, vv);
            }
            #pragma unroll
            for (int o = 16; o; o >>= 1) m = fmaxf(m, __shfl_xor_sync(0xffffffffu, m, o));
            float sum = 0.f;
            #pragma unroll
            for (int i = 0; i < 16; i++) { vals[i] = __expf(vals[i] - m); sum += vals[i]; }
            #pragma unroll
            for (int o = 16; o; o >>= 1) sum += __shfl_xor_sync(0xffffffffu, sum, o);
            const float inv = 1.f / sum;
            const size_t obase = ((size_t)(b * cH + h) * cS + sg) * cT;
            #pragma unroll
            for (int i = 0; i < 16; i++) {
                int t = lane + 32 * i;
                float p = vals[i] * inv;
                sc[row * cT + t] = p;
                attn_out[obase + t] = p;
            }
        }
    }
    __syncthreads();

    // ---- ctx = attn @ V: 2 rows x 4 dims per thread ----
    float cacc[2][4] = {};
    for (int tile = 0; tile < ntiles; tile++) {
        const int t0 = tile * TT;
        __syncthreads();
        for (int e = tid; e < TT * cHK; e += 256) {
            int tr = e >> 6, k = e & 63;
            KVs[tr * 65 + k] = Vb[base + (size_t)(t0 + tr) * rowStride + k];
        }
        __syncthreads();
        #pragma unroll 16
        for (int k = 0; k < TT; k++) {
            float a0 = sc[r0 * cT + t0 + k];
            float a1 = sc[r1 * cT + t0 + k];
            #pragma unroll
            for (int j = 0; j < 4; j++) {
                float vv = KVs[k * 65 + cg + 16 * j];
                cacc[0][j] += a0 * vv;
                cacc[1][j] += a1 * vv;
            }
        }
    }
    #pragma unroll
    for (int j = 0; j < 4; j++) {
        ctx[base + (size_t)(s0 + r0) * rowStride + cg + 16 * j] = cacc[0][j];
        ctx[base + (size_t)(s0 + r1) * rowStride + cg + 16 * j] = cacc[1][j];
    }
}

// ---------------- add-residual + layernorm ------------------------------------------
__global__ void add_ln_kernel(const float* __restrict__ a,
                              const float* __restrict__ res,
                              const float* __restrict__ g,
                              const float* __restrict__ be,
                              float* __restrict__ out)
{
    __shared__ float red[8];
    __shared__ float stat;
    const int row = blockIdx.x, tid = threadIdx.x;
    const size_t base = (size_t)row * cD;
    float v[4]; float s = 0.f;
    #pragma unroll
    for (int i = 0; i < 4; i++) {
        int c = tid + 256 * i;
        float t = a[base + c] + res[base + c];
        v[i] = t; s += t;
    }
    #pragma unroll
    for (int o = 16; o; o >>= 1) s += __shfl_xor_sync(0xffffffffu, s, o);
    if ((tid & 31) == 0) red[tid >> 5] = s;
    __syncthreads();
    if (tid == 0) { float t = 0; for (int i = 0; i < 8; i++) t += red[i]; stat = t * (1.f / cD); }
    __syncthreads();
    const float mu = stat;
    float s2 = 0.f;
    #pragma unroll
    for (int i = 0; i < 4; i++) { float d = v[i] - mu; s2 += d * d; }
    #pragma unroll
    for (int o = 16; o; o >>= 1) s2 += __shfl_xor_sync(0xffffffffu, s2, o);
    __syncthreads();
    if ((tid & 31) == 0) red[tid >> 5] = s2;
    __syncthreads();
    if (tid == 0) { float t = 0; for (int i = 0; i < 8; i++) t += red[i];
                    stat = rsqrtf(t * (1.f / cD) + 1e-6f); }
    __syncthreads();
    const float rstd = stat;
    #pragma unroll
    for (int i = 0; i < 4; i++) {
        int c = tid + 256 * i;
        out[base + c] = (v[i] - mu) * rstd * g[c] + be[c];
    }
}

// ---------------- launch ------------------------------------------------------------
extern "C" void kernel_launch(void* const* d_in, const int* in_sizes, int n_in,
                              void* d_out, int out_size)
{
    const float* x    = (const float*)d_in[0];
    const float* enc  = (const float*)d_in[1];
    const float* wq1  = (const float*)d_in[3];  const float* bq1 = (const float*)d_in[4];
    const float* wk1  = (const float*)d_in[5];  const float* bk1 = (const float*)d_in[6];
    const float* wv1  = (const float*)d_in[7];  const float* bv1 = (const float*)d_in[8];
    const float* wo1  = (const float*)d_in[9];  const float* bo1 = (const float*)d_in[10];
    const float* wq2  = (const float*)d_in[11]; const float* bq2 = (const float*)d_in[12];
    const float* wk2  = (const float*)d_in[13]; const float* bk2 = (const float*)d_in[14];
    const float* wv2  = (const float*)d_in[15]; const float* bv2 = (const float*)d_in[16];
    const float* wo2  = (const float*)d_in[17]; const float* bo2 = (const float*)d_in[18];
    const float* g1   = (const float*)d_in[19]; const float* be1 = (const float*)d_in[20];
    const float* g2   = (const float*)d_in[21]; const float* be2 = (const float*)d_in[22];
    const float* g3   = (const float*)d_in[23]; const float* be3 = (const float*)d_in[24];
    const float* wf1  = (const float*)d_in[25]; const float* bf1 = (const float*)d_in[26];
    const float* wf2  = (const float*)d_in[27]; const float* bf2 = (const float*)d_in[28];

    float* out   = (float*)d_out;
    float* attn1 = out + (size_t)cB * cS * cD;
    float* attn2 = attn1 + (size_t)cB * cH * cS * cS;

    float *q, *k, *v, *ctx, *tmp, *o1, *o2, *hb;
    __nv_bfloat16 *wbh, *wbl, *abh, *abl;
    cudaGetSymbolAddress((void**)&q,   g_q);
    cudaGetSymbolAddress((void**)&k,   g_k);
    cudaGetSymbolAddress((void**)&v,   g_v);
    cudaGetSymbolAddress((void**)&ctx, g_ctx);
    cudaGetSymbolAddress((void**)&tmp, g_tmp);
    cudaGetSymbolAddress((void**)&o1,  g_o1);
    cudaGetSymbolAddress((void**)&o2,  g_o2);
    cudaGetSymbolAddress((void**)&hb,  g_h);
    cudaGetSymbolAddress((void**)&wbh, g_wbh);
    cudaGetSymbolAddress((void**)&wbl, g_wbl);
    cudaGetSymbolAddress((void**)&abh, g_abh);
    cudaGetSymbolAddress((void**)&abl, g_abl);

    const size_t MEG = 1024 * 1024;
    // weight offsets (elements)
    __nv_bfloat16 *q1H = wbh + 0*MEG, *q1L = wbl + 0*MEG;
    __nv_bfloat16 *k1H = wbh + 1*MEG, *k1L = wbl + 1*MEG;
    __nv_bfloat16 *v1H = wbh + 2*MEG, *v1L = wbl + 2*MEG;
    __nv_bfloat16 *o1H = wbh + 3*MEG, *o1L = wbl + 3*MEG;
    __nv_bfloat16 *q2H = wbh + 4*MEG, *q2L = wbl + 4*MEG;
    __nv_bfloat16 *k2H = wbh + 5*MEG, *k2L = wbl + 5*MEG;
    __nv_bfloat16 *v2H = wbh + 6*MEG, *v2L = wbl + 6*MEG;
    __nv_bfloat16 *o2H = wbh + 7*MEG, *o2L = wbl + 7*MEG;
    __nv_bfloat16 *f1H = wbh + 8*MEG, *f1L = wbl + 8*MEG;
    __nv_bfloat16 *f2H = wbh + 12*MEG, *f2L = wbl + 12*MEG;
    // activation offsets
    const size_t ACT = (size_t)cB * cS * cD;            // 4M
    __nv_bfloat16 *xH   = abh + 0*ACT,  *xL   = abl + 0*ACT;
    __nv_bfloat16 *encH = abh + 1*ACT,  *encL = abl + 1*ACT;
    __nv_bfloat16 *ctxH = abh + 2*ACT,  *ctxL = abl + 2*ACT;
    __nv_bfloat16 *oa1H = abh + 3*ACT,  *oa1L = abl + 3*ACT;
    __nv_bfloat16 *oa2H = abh + 4*ACT,  *oa2L = abl + 4*ACT;
    __nv_bfloat16 *hbH  = abh + 5*ACT,  *hbL  = abl + 5*ACT;   // 16M elems

    const int smemAttn = (SB * cT + SB * 65 + TT * 65) * (int)sizeof(float);
    cudaFuncSetAttribute(attn_kernel<1>, cudaFuncAttributeMaxDynamicSharedMemorySize, smemAttn);
    cudaFuncSetAttribute(attn_kernel<0>, cudaFuncAttributeMaxDynamicSharedMemorySize, smemAttn);
    cudaFuncSetAttribute(mma_gemm, cudaFuncAttributeMaxDynamicSharedMemorySize, MM_SMEM);

    const int M = cB * cS;                      // 4096
    const int N4 = (int)(ACT / 4);              // 1M float4 per 4M-elem act
    const int N4h = N4 * 4;                     // hb: 16M elems
    dim3 tb(32, 8);
    dim3 tg1(cD / 32, cD / 32);
    dim3 tgF(cF / 32, cD / 32);
    dim3 tgF2(cD / 32, cF / 32);
    dim3 gP(cD / 128, M / 128);                 // (8, 32)
    dim3 gF1g(cF / 128, M / 128);               // (32, 32)
    dim3 gA(cS / SB, cH, cB);

    // ---- launches 0-4: minimal setup so launch #5 is the first mma_gemm (ncu -s 5) ----
    transpose_split_kernel<<<tg1, tb>>>(wq1, q1H, q1L, cD, cD);     // 0
    transpose_split_kernel<<<tg1, tb>>>(wk1, k1H, k1L, cD, cD);     // 1
    transpose_split_kernel<<<tg1, tb>>>(wv1, v1H, v1L, cD, cD);     // 2
    split_kernel<<<N4 / 256, 256>>>(x,   xH,   xL,   N4);           // 3
    split_kernel<<<N4 / 256, 256>>>(enc, encH, encL, N4);           // 4

    // ---- mha1 (self, causal) ----
    mma_gemm<<<gP, 256, MM_SMEM>>>(xH, xL, q1H, q1L, bq1, q, cD, cD, 0);   // 5 <- profiled
    mma_gemm<<<gP, 256, MM_SMEM>>>(xH, xL, k1H, k1L, bk1, k, cD, cD, 0);
    mma_gemm<<<gP, 256, MM_SMEM>>>(xH, xL, v1H, v1L, bv1, v, cD, cD, 0);
    // remaining weight prep (needed later; keeps first GEMM at launch index 5)
    transpose_split_kernel<<<tg1, tb>>>(wo1, o1H, o1L, cD, cD);
    transpose_split_kernel<<<tg1, tb>>>(wq2, q2H, q2L, cD, cD);
    transpose_split_kernel<<<tg1, tb>>>(wk2, k2H, k2L, cD, cD);
    transpose_split_kernel<<<tg1, tb>>>(wv2, v2H, v2L, cD, cD);
    transpose_split_kernel<<<tg1, tb>>>(wo2, o2H, o2L, cD, cD);
    transpose_split_kernel<<<tgF, tb>>>(wf1, f1H, f1L, cD, cF);
    transpose_split_kernel<<<tgF2, tb>>>(wf2, f2H, f2L, cF, cD);
    attn_kernel<1><<<gA, 256, smemAttn>>>(q, k, v, attn1, ctx);
    split_kernel<<<N4 / 256, 256>>>(ctx, ctxH, ctxL, N4);
    mma_gemm<<<gP, 256, MM_SMEM>>>(ctxH, ctxL, o1H, o1L, bo1, tmp, cD, cD, 0);
    add_ln_kernel<<<M, 256>>>(tmp, x, g1, be1, o1);
    split_kernel<<<N4 / 256, 256>>>(o1, oa1H, oa1L, N4);

    // ---- mha2 (cross) ----
    mma_gemm<<<gP, 256, MM_SMEM>>>(oa1H, oa1L, q2H, q2L, bq2, q, cD, cD, 0);
    mma_gemm<<<gP, 256, MM_SMEM>>>(encH, encL, k2H, k2L, bk2, k, cD, cD, 0);
    mma_gemm<<<gP, 256, MM_SMEM>>>(encH, encL, v2H, v2L, bv2, v, cD, cD, 0);
    attn_kernel<0><<<gA, 256, smemAttn>>>(q, k, v, attn2, ctx);
    split_kernel<<<N4 / 256, 256>>>(ctx, ctxH, ctxL, N4);
    mma_gemm<<<gP, 256, MM_SMEM>>>(ctxH, ctxL, o2H, o2L, bo2, tmp, cD, cD, 0);
    add_ln_kernel<<<M, 256>>>(tmp, o1, g2, be2, o2);
    split_kernel<<<N4 / 256, 256>>>(o2, oa2H, oa2L, N4);

    // ---- ffn ----
    mma_gemm<<<gF1g, 256, MM_SMEM>>>(oa2H, oa2L, f1H, f1L, bf1, hb, cF, cD, 1);
    split_kernel<<<N4h / 256, 256>>>(hb, hbH, hbL, N4h);
    mma_gemm<<<gP, 256, MM_SMEM>>>(hbH, hbL, f2H, f2L, bf2, tmp, cD, cF, 0);
    add_ln_kernel<<<M, 256>>>(tmp, o2, g3, be3, out);
}